// round 15
// baseline (speedup 1.0000x reference)
#include <cuda_runtime.h>

// Problem constants
#define NB   4096
#define NNUC 16
#define NELC 64

// Output offsets (floats): s_flat, v_flat, row, col, edge_attr, mask
#define OFF_V    8388608u
#define OFF_ROW  33554432u
#define OFF_COL  37748736u
#define OFF_ATTR 41943040u
#define OFF_MASK 54525952u

// Grid: blocks [0,8192) copy (S: 0..2047, V: 2048..8191), [8192,12288) edge.
// Copy chunks: 1024 float4 each, 4 per thread, fully coalesced.
#define S_COPY_BLOCKS 2048u
#define COPY_BLOCKS   8192u
#define TOTAL_BLOCKS  12288u

__global__ void __launch_bounds__(256)
fused_kernel(const float* __restrict__ s,
             const float* __restrict__ v,
             const float* __restrict__ ce,   // [NB, NELC, 3]
             const float* __restrict__ cn,   // [NNUC, 3]
             float* __restrict__ out)
{
    const unsigned blk = blockIdx.x;
    const unsigned tid = threadIdx.x;

    if (blk < COPY_BLOCKS) {
        // ---- reshape copies: streaming reads, write-through stores ---------
        const float4* src4;
        float4* dst4;
        unsigned base;
        if (blk < S_COPY_BLOCKS) {
            src4 = reinterpret_cast<const float4*>(s);
            dst4 = reinterpret_cast<float4*>(out);
            base = blk * 1024u;
        } else {
            src4 = reinterpret_cast<const float4*>(v);
            dst4 = reinterpret_cast<float4*>(out + OFF_V);
            base = (blk - S_COPY_BLOCKS) * 1024u;
        }
        float4 c0 = __ldcs(&src4[base + 0u * 256u + tid]);
        float4 c1 = __ldcs(&src4[base + 1u * 256u + tid]);
        float4 c2 = __ldcs(&src4[base + 2u * 256u + tid]);
        float4 c3 = __ldcs(&src4[base + 3u * 256u + tid]);
        __stwt(&dst4[base + 0u * 256u + tid], c0);
        __stwt(&dst4[base + 1u * 256u + tid], c1);
        __stwt(&dst4[base + 2u * 256u + tid], c2);
        __stwt(&dst4[base + 3u * 256u + tid], c3);
        return;
    }

    // ---- edge block: one batch b, everything generated from smem ----
    const unsigned b = blk - COPY_BLOCKS;

    __shared__ float ce_s[NELC * 3];   // 192 floats
    __shared__ float cn_s[NNUC * 3];   // 48 floats
    if (tid < 48u) {
        reinterpret_cast<float4*>(ce_s)[tid] =
            __ldg(reinterpret_cast<const float4*>(ce) + (size_t)b * 48u + tid);
    } else if (tid >= 64u && tid < 76u) {
        reinterpret_cast<float4*>(cn_s)[tid - 64u] =
            __ldg(reinterpret_cast<const float4*>(cn) + (tid - 64u));
    }
    __syncthreads();

    // edge_attr: 768 float4 per batch, 3 per thread, write-through stores
    // flat float f = (i*64 + j)*3 + c ; value = ce_s[j*3+c] - cn_s[i*3+c]
    float4* attr4 = reinterpret_cast<float4*>(out + OFF_ATTR) + (size_t)b * 768u;
#pragma unroll
    for (unsigned k = 0; k < 3; ++k) {
        unsigned n  = k * 256u + tid;           // 0..767
        unsigned i  = n / 48u;                  // nucleus
        unsigned f0 = 4u * n - 192u * i;        // elec-chunk float offset, %4==0
        float4 e = *reinterpret_cast<const float4*>(ce_s + f0);  // conflict-free
        const float* cni = cn_s + i * 3u;
        unsigned c0 = f0 % 3u;
        float n0 = cni[c0];
        float n1 = cni[(c0 + 1u) % 3u];
        float n2 = cni[(c0 + 2u) % 3u];
        __stwt(&attr4[n], make_float4(e.x - n0, e.y - n1, e.z - n2, e.w - n0));
    }

    // row / col / mask: 1024 pairs per batch, 4 per thread
    unsigned p0 = tid * 4u;
    unsigned i  = p0 >> 6;                  // nucleus (quads never cross i)
    unsigned j0 = p0 & 63u;

    float nx = cn_s[i * 3u + 0u];
    float ny = cn_s[i * 3u + 1u];
    float nz = cn_s[i * 3u + 2u];

    float m[4];
#pragma unroll
    for (unsigned k = 0; k < 4; ++k) {
        unsigned j = j0 + k;
        float dx = ce_s[j * 3u + 0u] - nx;
        float dy = ce_s[j * 3u + 1u] - ny;
        float dz = ce_s[j * 3u + 2u] - nz;
        float d2 = dx * dx + dy * dy + dz * dz;
        m[k] = (sqrtf(d2) < 5.0f) ? 1.0f : 0.0f;
    }

    float rowf = (float)(b * 16u + i);      // exact in f32
    float colb = (float)(b * 64u + j0);     // exact in f32

    size_t pb = (size_t)b * 1024u + p0;
    __stwt(reinterpret_cast<float4*>(out + OFF_ROW + pb),
           make_float4(rowf, rowf, rowf, rowf));
    __stwt(reinterpret_cast<float4*>(out + OFF_COL + pb),
           make_float4(colb, colb + 1.0f, colb + 2.0f, colb + 3.0f));
    __stwt(reinterpret_cast<float4*>(out + OFF_MASK + pb),
           make_float4(m[0], m[1], m[2], m[3]));
}

extern "C" void kernel_launch(void* const* d_in, const int* in_sizes, int n_in,
                              void* d_out, int out_size)
{
    const float* s  = nullptr;   // s_nuc      8,388,608
    const float* v  = nullptr;   // v_nuc     25,165,824
    const float* ce = nullptr;   // coord_elec   786,432
    const float* cn = nullptr;   // coord_nuc         48
    for (int k = 0; k < n_in; ++k) {
        switch (in_sizes[k]) {
            case 8388608:  s  = (const float*)d_in[k]; break;
            case 25165824: v  = (const float*)d_in[k]; break;
            case 786432:   ce = (const float*)d_in[k]; break;
            case 48:       cn = (const float*)d_in[k]; break;
            default: break;
        }
    }

    fused_kernel<<<TOTAL_BLOCKS, 256>>>(s, v, ce, cn, (float*)d_out);
}

// round 16
// speedup vs baseline: 1.0515x; 1.0515x over previous
#include <cuda_runtime.h>

// Problem constants
#define NB   4096
#define NNUC 16
#define NELC 64

// Output offsets (floats): s_flat, v_flat, row, col, edge_attr, mask
#define OFF_V    8388608u
#define OFF_ROW  33554432u
#define OFF_COL  37748736u
#define OFF_ATTR 41943040u
#define OFF_MASK 54525952u

// Grid: blocks [0,8192) copy (S: 0..2047, V: 2048..8191), [8192,12288) edge.
// Copy chunks: 1024 float4 each, 4 per thread, fully coalesced.
#define S_COPY_BLOCKS 2048u
#define COPY_BLOCKS   8192u
#define TOTAL_BLOCKS  12288u

__global__ void __launch_bounds__(256)
fused_kernel(const float* __restrict__ s,
             const float* __restrict__ v,
             const float* __restrict__ ce,   // [NB, NELC, 3]
             const float* __restrict__ cn,   // [NNUC, 3]
             float* __restrict__ out)
{
    const unsigned blk = blockIdx.x;
    const unsigned tid = threadIdx.x;

    if (blk < COPY_BLOCKS) {
        // ---- reshape copies: fully streaming (zero reuse either side) ------
        const float4* src4;
        float4* dst4;
        unsigned base;
        if (blk < S_COPY_BLOCKS) {
            src4 = reinterpret_cast<const float4*>(s);
            dst4 = reinterpret_cast<float4*>(out);
            base = blk * 1024u;
        } else {
            src4 = reinterpret_cast<const float4*>(v);
            dst4 = reinterpret_cast<float4*>(out + OFF_V);
            base = (blk - S_COPY_BLOCKS) * 1024u;
        }
        float4 c0 = __ldcs(&src4[base + 0u * 256u + tid]);
        float4 c1 = __ldcs(&src4[base + 1u * 256u + tid]);
        float4 c2 = __ldcs(&src4[base + 2u * 256u + tid]);
        float4 c3 = __ldcs(&src4[base + 3u * 256u + tid]);
        __stcs(&dst4[base + 0u * 256u + tid], c0);
        __stcs(&dst4[base + 1u * 256u + tid], c1);
        __stcs(&dst4[base + 2u * 256u + tid], c2);
        __stcs(&dst4[base + 3u * 256u + tid], c3);
        return;
    }

    // ---- edge block: one batch b, everything generated from smem ----
    const unsigned b = blk - COPY_BLOCKS;

    __shared__ float ce_s[NELC * 3];   // 192 floats
    __shared__ float cn_s[NNUC * 3];   // 48 floats
    if (tid < 48u) {
        reinterpret_cast<float4*>(ce_s)[tid] =
            __ldg(reinterpret_cast<const float4*>(ce) + (size_t)b * 48u + tid);
    } else if (tid >= 64u && tid < 76u) {
        reinterpret_cast<float4*>(cn_s)[tid - 64u] =
            __ldg(reinterpret_cast<const float4*>(cn) + (tid - 64u));
    }
    __syncthreads();

    // edge_attr: 768 float4 per batch, 3 per thread, coalesced streaming stores
    // flat float f = (i*64 + j)*3 + c ; value = ce_s[j*3+c] - cn_s[i*3+c]
    float4* attr4 = reinterpret_cast<float4*>(out + OFF_ATTR) + (size_t)b * 768u;
#pragma unroll
    for (unsigned k = 0; k < 3; ++k) {
        unsigned n  = k * 256u + tid;           // 0..767
        unsigned i  = n / 48u;                  // nucleus
        unsigned f0 = 4u * n - 192u * i;        // elec-chunk float offset, %4==0
        float4 e = *reinterpret_cast<const float4*>(ce_s + f0);  // conflict-free
        const float* cni = cn_s + i * 3u;
        unsigned c0 = f0 % 3u;
        float n0 = cni[c0];
        float n1 = cni[(c0 + 1u) % 3u];
        float n2 = cni[(c0 + 2u) % 3u];
        __stcs(&attr4[n], make_float4(e.x - n0, e.y - n1, e.z - n2, e.w - n0));
    }

    // row / col / mask: 1024 pairs per batch, 4 per thread
    unsigned p0 = tid * 4u;
    unsigned i  = p0 >> 6;                  // nucleus (quads never cross i)
    unsigned j0 = p0 & 63u;

    float nx = cn_s[i * 3u + 0u];
    float ny = cn_s[i * 3u + 1u];
    float nz = cn_s[i * 3u + 2u];

    float m[4];
#pragma unroll
    for (unsigned k = 0; k < 4; ++k) {
        unsigned j = j0 + k;
        float dx = ce_s[j * 3u + 0u] - nx;
        float dy = ce_s[j * 3u + 1u] - ny;
        float dz = ce_s[j * 3u + 2u] - nz;
        float d2 = dx * dx + dy * dy + dz * dz;
        m[k] = (sqrtf(d2) < 5.0f) ? 1.0f : 0.0f;
    }

    float rowf = (float)(b * 16u + i);      // exact in f32
    float colb = (float)(b * 64u + j0);     // exact in f32

    size_t pb = (size_t)b * 1024u + p0;
    __stcs(reinterpret_cast<float4*>(out + OFF_ROW + pb),
           make_float4(rowf, rowf, rowf, rowf));
    __stcs(reinterpret_cast<float4*>(out + OFF_COL + pb),
           make_float4(colb, colb + 1.0f, colb + 2.0f, colb + 3.0f));
    __stcs(reinterpret_cast<float4*>(out + OFF_MASK + pb),
           make_float4(m[0], m[1], m[2], m[3]));
}

extern "C" void kernel_launch(void* const* d_in, const int* in_sizes, int n_in,
                              void* d_out, int out_size)
{
    const float* s  = nullptr;   // s_nuc      8,388,608
    const float* v  = nullptr;   // v_nuc     25,165,824
    const float* ce = nullptr;   // coord_elec   786,432
    const float* cn = nullptr;   // coord_nuc         48
    for (int k = 0; k < n_in; ++k) {
        switch (in_sizes[k]) {
            case 8388608:  s  = (const float*)d_in[k]; break;
            case 25165824: v  = (const float*)d_in[k]; break;
            case 786432:   ce = (const float*)d_in[k]; break;
            case 48:       cn = (const float*)d_in[k]; break;
            default: break;
        }
    }

    fused_kernel<<<TOTAL_BLOCKS, 256>>>(s, v, ce, cn, (float*)d_out);
}